// round 7
// baseline (speedup 1.0000x reference)
#include <cuda_runtime.h>
#include <cuda_bf16.h>
#include <cstdint>
#include <cstddef>

// Problem dims
#define BB 8
#define TT 256
#define UU 64
#define HH 640
#define VV 1025
#define NROWS (BB*TT*UU)   // 131072
#define NPAD 1024          // GEMM covers cols 0..1023; col 1024 via GEMV in k_tanhA

// Scratch (device globals: allocation-free rule)
__device__ __nv_bfloat16 g_A[(size_t)NROWS * HH];     // tanh(enc+dec) bf16, 168MB
__device__ __nv_bfloat16 g_Wb[(size_t)NPAD * HH];     // W rows 0..1023 bf16
__device__ float         g_blank[NROWS];              // logit for vocab col 1024

// ---------------------------------------------------------------------------
// Helpers
// ---------------------------------------------------------------------------
__device__ __forceinline__ uint32_t smem_u32(const void* p) {
    return (uint32_t)__cvta_generic_to_shared(p);
}
__device__ __forceinline__ void cp16(uint32_t s, const void* g) {
    asm volatile("cp.async.cg.shared.global [%0], [%1], 16;\n" :: "r"(s), "l"(g));
}
__device__ __forceinline__ void cp_commit() { asm volatile("cp.async.commit_group;\n" ::: "memory"); }
__device__ __forceinline__ void cp_wait0() { asm volatile("cp.async.wait_group 0;\n" ::: "memory"); }
__device__ __forceinline__ void cp_wait1() { asm volatile("cp.async.wait_group 1;\n" ::: "memory"); }

__device__ __forceinline__ void ldm4(uint32_t* r, uint32_t addr) {
    asm volatile("ldmatrix.sync.aligned.m8n8.x4.shared.b16 {%0,%1,%2,%3}, [%4];"
        : "=r"(r[0]), "=r"(r[1]), "=r"(r[2]), "=r"(r[3]) : "r"(addr));
}
__device__ __forceinline__ void mma16816(float* c, const uint32_t* a, const uint32_t* b) {
    asm volatile(
        "mma.sync.aligned.m16n8k16.row.col.f32.bf16.bf16.f32 "
        "{%0,%1,%2,%3}, {%4,%5,%6,%7}, {%8,%9}, {%0,%1,%2,%3};\n"
        : "+f"(c[0]), "+f"(c[1]), "+f"(c[2]), "+f"(c[3])
        : "r"(a[0]), "r"(a[1]), "r"(a[2]), "r"(a[3]), "r"(b[0]), "r"(b[1]));
}
__device__ __forceinline__ void cluster_sync() {
    asm volatile("barrier.cluster.arrive.aligned;" ::: "memory");
    asm volatile("barrier.cluster.wait.aligned;" ::: "memory");
}

// ---------------------------------------------------------------------------
// K0: W fp32 -> bf16 (rows 0..1023)
// ---------------------------------------------------------------------------
__global__ void k_convW(const float* __restrict__ W) {
    int i = (blockIdx.x * blockDim.x + threadIdx.x) * 2;
    if (i < NPAD * HH) {
        float2 w = *(const float2*)(W + i);
        *(__nv_bfloat162*)(g_Wb + i) = __floats2bfloat162_rn(w.x, w.y);
    }
}

// ---------------------------------------------------------------------------
// K1: A = tanh(enc+dec) -> bf16 scratch, fused GEMV for blank column 1024
// One warp per row; 8 rows per 256-thread block.
// ---------------------------------------------------------------------------
__global__ void __launch_bounds__(256) k_tanhA(
    const float* __restrict__ enc, const float* __restrict__ dec,
    const float* __restrict__ W, const float* __restrict__ bias)
{
    int warp = threadIdx.x >> 5, lane = threadIdx.x & 31;
    int row  = blockIdx.x * 8 + warp;
    int b = row >> 14;
    int t = (row >> 6) & 255;
    int u = row & 63;
    const float* e  = enc + (size_t)(b * TT + t) * HH;
    const float* d  = dec + (size_t)(b * UU + u) * HH;
    const float* wl = W + (size_t)NPAD * HH;   // W[1024,:]
    __nv_bfloat16* arow = g_A + (size_t)row * HH;

    float acc = 0.f;
#pragma unroll
    for (int j = 0; j < 10; j++) {
        int k = j * 64 + lane * 2;
        float2 ev = *(const float2*)(e + k);
        float2 dv = *(const float2*)(d + k);
        float x0 = ev.x + dv.x, x1 = ev.y + dv.y;
        float h0, h1;
        asm("tanh.approx.f32 %0, %1;" : "=f"(h0) : "f"(x0));
        asm("tanh.approx.f32 %0, %1;" : "=f"(h1) : "f"(x1));
        *(__nv_bfloat162*)(arow + k) = __floats2bfloat162_rn(h0, h1);
        float2 wv = *(const float2*)(wl + k);
        acc = fmaf(h0, wv.x, acc);
        acc = fmaf(h1, wv.y, acc);
    }
#pragma unroll
    for (int o = 16; o; o >>= 1) acc += __shfl_xor_sync(0xffffffffu, acc, o);
    if (lane == 0) g_blank[row] = acc + bias[1024];
}

// ---------------------------------------------------------------------------
// K2: fused GEMM + log_softmax.
// Cluster (2,1,1): CTA rank r covers rows [m0,m0+128), cols [r*512, r*512+512)
// as 4 sub-tiles of 128x128.  mma.sync m16n8k16 bf16, ldmatrix fragment loads,
// BK=64, 2-stage cp.async double buffer with cross-sub prefetch.
// Per sub: online (rowmax, sumexp) update in smem; logits+bias -> gmem.
// End: DSMEM exchange of (m,s) with peer -> lse; rewrite (L2-resident) tile
// subtracting lse.  Rank 1 also owns blank col 1024 (from g_blank).
// ---------------------------------------------------------------------------
#define PADE 72                 // bf16 elems per smem row (64 data + 8 pad) = 144B
#define STG_BYTES (128*PADE*2)  // 18432 per tile stage
#define MA_A0 0
#define MA_A1 STG_BYTES
#define MA_B0 (2*STG_BYTES)
#define MA_B1 (3*STG_BYTES)
#define RED_OFF (4*STG_BYTES)   // 73728
#define SMEM_TOTAL (RED_OFF + 4096)

__global__ void __launch_bounds__(256) __cluster_dims__(2, 1, 1)
k_gemm(const float* __restrict__ bias, float* __restrict__ out)
{
    extern __shared__ char smem[];
    uint32_t sbase = smem_u32(smem);
    int tid = threadIdx.x;
    int wid = tid >> 5, lane = tid & 31;
    int gid = lane >> 2, tig = lane & 3;
    int la = lane & 7, lb = (lane >> 3) & 1, lc = (lane >> 4) & 1;
    int m0 = blockIdx.y * 128;
    uint32_t rank;
    asm("mov.u32 %0, %%cluster_ctarank;" : "=r"(rank));
    int n0 = (int)rank * 512;

    int m_base = (wid & 3) * 32;   // 4 warps along M (32 rows each)
    int n_base = (wid >> 2) * 64;  // 2 warps along N (64 cols each)

    // reduction smem
    float* s_m2   = (float*)(smem + RED_OFF);           // [2][128]
    float* s_s2   = (float*)(smem + RED_OFF + 1024);    // [2][128]
    float* s_rmax = (float*)(smem + RED_OFF + 2048);    // [128]
    float* s_mrun = (float*)(smem + RED_OFF + 2560);    // [128]
    float* s_srun = (float*)(smem + RED_OFF + 3072);    // [128]
    float* s_lse  = (float*)(smem + RED_OFF + 3584);    // [128]

    const uint32_t aoff[2] = {MA_A0, MA_A1};
    const uint32_t boff[2] = {MA_B0, MA_B1};

    const __nv_bfloat16* Abase = g_A + (size_t)m0 * HH;

    auto load_stage = [&](int sub, int it, int s) {
        uint32_t ab = sbase + aoff[s];
        uint32_t bb = sbase + boff[s];
        const __nv_bfloat16* Ag = Abase + it * 64;
        const __nv_bfloat16* Bg = g_Wb + (size_t)(n0 + sub * 128) * HH + it * 64;
#pragma unroll
        for (int j = 0; j < 4; j++) {      // 128 rows x 8 chunks of 16B
            int c = tid + j * 256;
            int r = c >> 3, cc = c & 7;
            cp16(ab + r * (PADE*2) + cc * 16, Ag + (size_t)r * HH + cc * 8);
        }
#pragma unroll
        for (int j = 0; j < 4; j++) {
            int c = tid + j * 256;
            int r = c >> 3, cc = c & 7;
            cp16(bb + r * (PADE*2) + cc * 16, Bg + (size_t)r * HH + cc * 8);
        }
        cp_commit();
    };

    // ldmatrix per-thread address bases (within a stage)
    uint32_t aAdd = (uint32_t)(m_base + la + lb * 8) * 144 + (uint32_t)lc * 16;
    uint32_t bAdd = (uint32_t)(n_base + la + lc * 8) * 144 + (uint32_t)lb * 16;

    // local row indices rl[c], c = mt*2 + hi  (row = m_base + mt*16 + hi*8 + gid)
    int rl[4];
#pragma unroll
    for (int c = 0; c < 4; c++) rl[c] = m_base + (c >> 1) * 16 + (c & 1) * 8 + gid;

    load_stage(0, 0, 0);
    load_stage(0, 1, 1);

    for (int sub = 0; sub < 4; sub++) {
        float acc[2][8][4];
#pragma unroll
        for (int mt = 0; mt < 2; mt++)
#pragma unroll
            for (int nt = 0; nt < 8; nt++)
#pragma unroll
                for (int q = 0; q < 4; q++) acc[mt][nt][q] = 0.f;

        for (int kc = 0; kc < 10; kc++) {
            int s = kc & 1;
            if (sub == 3 && kc == 9) cp_wait0(); else cp_wait1();
            __syncthreads();

            uint32_t aB = sbase + aoff[s] + aAdd;
            uint32_t bB = sbase + boff[s] + bAdd;
#pragma unroll
            for (int ks = 0; ks < 4; ks++) {
                uint32_t a[2][4], b[8][2];
                ldm4(a[0], aB + ks * 32);
                ldm4(a[1], aB + 16 * 144 + ks * 32);
#pragma unroll
                for (int p = 0; p < 4; p++)
                    ldm4(&b[2 * p][0], bB + p * (16 * 144) + ks * 32);
#pragma unroll
                for (int mt = 0; mt < 2; mt++)
#pragma unroll
                    for (int nt = 0; nt < 8; nt++)
                        mma16816(acc[mt][nt], a[mt], b[nt]);
            }
            __syncthreads();
            if (kc + 2 < 10)      load_stage(sub, kc + 2, s);
            else if (sub < 3)     load_stage(sub + 1, kc + 2 - 10, s);
        }

        // ---- epilogue for this sub: bias add, online (max,sum), store logits
        int colb = n0 + sub * 128 + n_base;
#pragma unroll
        for (int nt = 0; nt < 8; nt++) {
            float2 bi = *(const float2*)(bias + colb + nt * 8 + tig * 2);
#pragma unroll
            for (int mt = 0; mt < 2; mt++) {
                acc[mt][nt][0] += bi.x; acc[mt][nt][1] += bi.y;
                acc[mt][nt][2] += bi.x; acc[mt][nt][3] += bi.y;
            }
        }

        // per-thread row-class max
        float mx[4] = {-1e30f, -1e30f, -1e30f, -1e30f};
#pragma unroll
        for (int mt = 0; mt < 2; mt++)
#pragma unroll
            for (int nt = 0; nt < 8; nt++) {
                mx[mt*2+0] = fmaxf(mx[mt*2+0], fmaxf(acc[mt][nt][0], acc[mt][nt][1]));
                mx[mt*2+1] = fmaxf(mx[mt*2+1], fmaxf(acc[mt][nt][2], acc[mt][nt][3]));
            }
#pragma unroll
        for (int c = 0; c < 4; c++) {
            mx[c] = fmaxf(mx[c], __shfl_xor_sync(0xffffffffu, mx[c], 1));
            mx[c] = fmaxf(mx[c], __shfl_xor_sync(0xffffffffu, mx[c], 2));
        }
        int half = wid >> 2;
        if (tig == 0) {
#pragma unroll
            for (int c = 0; c < 4; c++) s_m2[half * 128 + rl[c]] = mx[c];
        }
        __syncthreads();
        if (tid < 128) s_rmax[tid] = fmaxf(s_m2[tid], s_m2[128 + tid]);
        __syncthreads();

        float rm[4], sm[4] = {0.f, 0.f, 0.f, 0.f};
#pragma unroll
        for (int c = 0; c < 4; c++) rm[c] = s_rmax[rl[c]];
#pragma unroll
        for (int mt = 0; mt < 2; mt++)
#pragma unroll
            for (int nt = 0; nt < 8; nt++) {
                sm[mt*2+0] += __expf(acc[mt][nt][0] - rm[mt*2+0])
                            + __expf(acc[mt][nt][1] - rm[mt*2+0]);
                sm[mt*2+1] += __expf(acc[mt][nt][2] - rm[mt*2+1])
                            + __expf(acc[mt][nt][3] - rm[mt*2+1]);
            }
#pragma unroll
        for (int c = 0; c < 4; c++) {
            sm[c] += __shfl_xor_sync(0xffffffffu, sm[c], 1);
            sm[c] += __shfl_xor_sync(0xffffffffu, sm[c], 2);
        }
        if (tig == 0) {
#pragma unroll
            for (int c = 0; c < 4; c++) s_s2[half * 128 + rl[c]] = sm[c];
        }
        __syncthreads();
        if (tid < 128) {
            float msub = s_rmax[tid];
            float ssub = s_s2[tid] + s_s2[128 + tid];
            if (sub == 0) { s_mrun[tid] = msub; s_srun[tid] = ssub; }
            else {
                float mo = s_mrun[tid];
                float M = fmaxf(mo, msub);
                s_srun[tid] = s_srun[tid] * __expf(mo - M) + ssub * __expf(msub - M);
                s_mrun[tid] = M;
            }
        }

        // store biased logits
#pragma unroll
        for (int mt = 0; mt < 2; mt++)
#pragma unroll
            for (int nt = 0; nt < 8; nt++) {
                int col = colb + nt * 8 + tig * 2;
                float* p0 = out + (size_t)(m0 + rl[mt*2+0]) * VV + col;
                p0[0] = acc[mt][nt][0]; p0[1] = acc[mt][nt][1];
                float* p1 = out + (size_t)(m0 + rl[mt*2+1]) * VV + col;
                p1[0] = acc[mt][nt][2]; p1[1] = acc[mt][nt][3];
            }
        __syncthreads();   // s_m2/s_s2/s_rmax reused next sub
    }

    // ---- fold blank into rank-1 partials (counted exactly once) ----
    if (rank == 1 && tid < 128) {
        float bl = g_blank[m0 + tid];
        float mo = s_mrun[tid];
        float M = fmaxf(mo, bl);
        s_srun[tid] = s_srun[tid] * __expf(mo - M) + __expf(bl - M);
        s_mrun[tid] = M;
    }
    __syncthreads();

    // ---- cluster exchange: lse = merge(local, peer) ----
    cluster_sync();
    if (tid < 128) {
        uint32_t lm = sbase + RED_OFF + 2560 + tid * 4;   // s_mrun[tid]
        uint32_t ls = sbase + RED_OFF + 3072 + tid * 4;   // s_srun[tid]
        uint32_t peer = rank ^ 1u, rm_, rs_;
        asm("mapa.shared::cluster.u32 %0, %1, %2;" : "=r"(rm_) : "r"(lm), "r"(peer));
        asm("mapa.shared::cluster.u32 %0, %1, %2;" : "=r"(rs_) : "r"(ls), "r"(peer));
        float pm, ps;
        asm volatile("ld.shared::cluster.f32 %0, [%1];" : "=f"(pm) : "r"(rm_));
        asm volatile("ld.shared::cluster.f32 %0, [%1];" : "=f"(ps) : "r"(rs_));
        float ml = s_mrun[tid], sl = s_srun[tid];
        float M = fmaxf(ml, pm);
        float S = sl * __expf(ml - M) + ps * __expf(pm - M);
        s_lse[tid] = M + logf(S);
    }
    __syncthreads();

    // ---- rewrite: subtract lse (tile is L2-resident) ----
    float l[4];
#pragma unroll
    for (int c = 0; c < 4; c++) l[c] = s_lse[rl[c]];
#pragma unroll
    for (int sub = 0; sub < 4; sub++) {
#pragma unroll
        for (int nt = 0; nt < 8; nt++) {
            int col = n0 + sub * 128 + n_base + nt * 8 + tig * 2;
#pragma unroll
            for (int c = 0; c < 4; c++) {
                float* p = out + (size_t)(m0 + rl[c]) * VV + col;
                p[0] = p[0] - l[c];
                p[1] = p[1] - l[c];
            }
        }
    }
    if (rank == 1 && tid < 128)
        out[(size_t)(m0 + tid) * VV + 1024] = g_blank[m0 + tid] - s_lse[tid];

    cluster_sync();   // keep smem alive until peer finished its DSMEM reads
}

// ---------------------------------------------------------------------------
extern "C" void kernel_launch(void* const* d_in, const int* in_sizes, int n_in,
                              void* d_out, int out_size) {
    (void)in_sizes; (void)n_in; (void)out_size;
    const float* enc  = (const float*)d_in[0];
    const float* dec  = (const float*)d_in[1];
    const float* W    = (const float*)d_in[2];
    const float* bias = (const float*)d_in[3];
    float* out = (float*)d_out;

    k_convW<<<(NPAD * HH / 2 + 255) / 256, 256>>>(W);
    k_tanhA<<<NROWS / 8, 256>>>(enc, dec, W, bias);

    cudaFuncSetAttribute(k_gemm, cudaFuncAttributeMaxDynamicSharedMemorySize, SMEM_TOTAL);
    dim3 grid(2, NROWS / 128);   // cluster pairs along x
    k_gemm<<<grid, 256, SMEM_TOTAL>>>(bias, out);
}

// round 10
// speedup vs baseline: 1.3036x; 1.3036x over previous
#include <cuda_runtime.h>
#include <cuda_bf16.h>
#include <cstdint>
#include <cstddef>

// Problem dims
#define BB 8
#define TT 256
#define UU 64
#define HH 640
#define VV 1025
#define NROWS (BB*TT*UU)   // 131072
#define NPAD 1024          // GEMM covers cols 0..1023; col 1024 via GEMV in k_tanhA

// Scratch (device globals: allocation-free rule)
__device__ __nv_bfloat16 g_A[(size_t)NROWS * HH];     // tanh(enc+dec) bf16, 168MB
__device__ __nv_bfloat16 g_Wb[(size_t)NPAD * HH];     // W rows 0..1023 bf16

// ---------------------------------------------------------------------------
// Helpers
// ---------------------------------------------------------------------------
__device__ __forceinline__ uint32_t smem_u32(const void* p) {
    return (uint32_t)__cvta_generic_to_shared(p);
}
__device__ __forceinline__ void cp16(uint32_t s, const void* g) {
    asm volatile("cp.async.cg.shared.global [%0], [%1], 16;\n" :: "r"(s), "l"(g));
}
__device__ __forceinline__ void cp_commit() { asm volatile("cp.async.commit_group;\n" ::: "memory"); }
__device__ __forceinline__ void cp_wait0() { asm volatile("cp.async.wait_group 0;\n" ::: "memory"); }
__device__ __forceinline__ void cp_wait1() { asm volatile("cp.async.wait_group 1;\n" ::: "memory"); }

__device__ __forceinline__ void ldm4(uint32_t* r, uint32_t addr) {
    asm volatile("ldmatrix.sync.aligned.m8n8.x4.shared.b16 {%0,%1,%2,%3}, [%4];"
        : "=r"(r[0]), "=r"(r[1]), "=r"(r[2]), "=r"(r[3]) : "r"(addr));
}
__device__ __forceinline__ void mma16816(float* c, const uint32_t* a, const uint32_t* b) {
    asm volatile(
        "mma.sync.aligned.m16n8k16.row.col.f32.bf16.bf16.f32 "
        "{%0,%1,%2,%3}, {%4,%5,%6,%7}, {%8,%9}, {%0,%1,%2,%3};\n"
        : "+f"(c[0]), "+f"(c[1]), "+f"(c[2]), "+f"(c[3])
        : "r"(a[0]), "r"(a[1]), "r"(a[2]), "r"(a[3]), "r"(b[0]), "r"(b[1]));
}

// ---------------------------------------------------------------------------
// K0: W fp32 -> bf16 (rows 0..1023)
// ---------------------------------------------------------------------------
__global__ void k_convW(const float* __restrict__ W) {
    int i = (blockIdx.x * blockDim.x + threadIdx.x) * 2;
    if (i < NPAD * HH) {
        float2 w = *(const float2*)(W + i);
        *(__nv_bfloat162*)(g_Wb + i) = __floats2bfloat162_rn(w.x, w.y);
    }
}

// ---------------------------------------------------------------------------
// K1: A = tanh(enc+dec) -> bf16 scratch, fused GEMV for blank column 1024
// (blank logit written straight into out[row*VV+1024]; k_lsm normalizes it)
// ---------------------------------------------------------------------------
__global__ void __launch_bounds__(256) k_tanhA(
    const float* __restrict__ enc, const float* __restrict__ dec,
    const float* __restrict__ W, const float* __restrict__ bias,
    float* __restrict__ out)
{
    int warp = threadIdx.x >> 5, lane = threadIdx.x & 31;
    int row  = blockIdx.x * 8 + warp;
    int b = row >> 14;
    int t = (row >> 6) & 255;
    int u = row & 63;
    const float* e  = enc + (size_t)(b * TT + t) * HH;
    const float* d  = dec + (size_t)(b * UU + u) * HH;
    const float* wl = W + (size_t)NPAD * HH;   // W[1024,:]
    __nv_bfloat16* arow = g_A + (size_t)row * HH;

    float acc = 0.f;
#pragma unroll
    for (int j = 0; j < 10; j++) {
        int k = j * 64 + lane * 2;
        float2 ev = *(const float2*)(e + k);
        float2 dv = *(const float2*)(d + k);
        float x0 = ev.x + dv.x, x1 = ev.y + dv.y;
        float h0, h1;
        asm("tanh.approx.f32 %0, %1;" : "=f"(h0) : "f"(x0));
        asm("tanh.approx.f32 %0, %1;" : "=f"(h1) : "f"(x1));
        *(__nv_bfloat162*)(arow + k) = __floats2bfloat162_rn(h0, h1);
        float2 wv = *(const float2*)(wl + k);
        acc = fmaf(h0, wv.x, acc);
        acc = fmaf(h1, wv.y, acc);
    }
#pragma unroll
    for (int o = 16; o; o >>= 1) acc += __shfl_xor_sync(0xffffffffu, acc, o);
    if (lane == 0) out[(size_t)row * VV + 1024] = acc + bias[1024];
}

// ---------------------------------------------------------------------------
// K2: plain GEMM (R2 structure) with ldmatrix fragment loads (R7 mainloop).
// CTA covers rows [m0,m0+128), cols [n0,n0+512) as 4 sub-tiles of 128x128.
// BK=64, 2-stage cp.async double buffer with cross-sub prefetch.
// Epilogue: bias add, store logits. No clusters, no softmax here.
// ---------------------------------------------------------------------------
#define PADE 72                 // bf16 elems per smem row (64 data + 8 pad) = 144B
#define STG_BYTES (128*PADE*2)  // 18432 per tile stage
#define MA_A0 0
#define MA_A1 STG_BYTES
#define MA_B0 (2*STG_BYTES)
#define MA_B1 (3*STG_BYTES)
#define SMEM_TOTAL (4*STG_BYTES)   // 73728

__global__ void __launch_bounds__(256) k_gemm(const float* __restrict__ bias,
                                              float* __restrict__ out)
{
    extern __shared__ char smem[];
    uint32_t sbase = smem_u32(smem);
    int tid = threadIdx.x;
    int wid = tid >> 5, lane = tid & 31;
    int gid = lane >> 2, tig = lane & 3;
    int la = lane & 7, lb = (lane >> 3) & 1, lc = (lane >> 4) & 1;
    int m0 = blockIdx.y * 128;
    int n0 = blockIdx.x * 512;

    int m_base = (wid & 3) * 32;   // 4 warps along M (32 rows each)
    int n_base = (wid >> 2) * 64;  // 2 warps along N (64 cols each)

    const uint32_t aoff[2] = {MA_A0, MA_A1};
    const uint32_t boff[2] = {MA_B0, MA_B1};

    const __nv_bfloat16* Abase = g_A + (size_t)m0 * HH;

    auto load_stage = [&](int sub, int it, int s) {
        uint32_t ab = sbase + aoff[s];
        uint32_t bb = sbase + boff[s];
        const __nv_bfloat16* Ag = Abase + it * 64;
        const __nv_bfloat16* Bg = g_Wb + (size_t)(n0 + sub * 128) * HH + it * 64;
#pragma unroll
        for (int j = 0; j < 4; j++) {      // 128 rows x 8 chunks of 16B
            int c = tid + j * 256;
            int r = c >> 3, cc = c & 7;
            cp16(ab + r * (PADE*2) + cc * 16, Ag + (size_t)r * HH + cc * 8);
        }
#pragma unroll
        for (int j = 0; j < 4; j++) {
            int c = tid + j * 256;
            int r = c >> 3, cc = c & 7;
            cp16(bb + r * (PADE*2) + cc * 16, Bg + (size_t)r * HH + cc * 8);
        }
        cp_commit();
    };

    // ldmatrix per-thread address bases (within a stage)
    uint32_t aAdd = (uint32_t)(m_base + la + lb * 8) * 144 + (uint32_t)lc * 16;
    uint32_t bAdd = (uint32_t)(n_base + la + lc * 8) * 144 + (uint32_t)lb * 16;

    load_stage(0, 0, 0);
    load_stage(0, 1, 1);

    for (int sub = 0; sub < 4; sub++) {
        float acc[2][8][4];
#pragma unroll
        for (int mt = 0; mt < 2; mt++)
#pragma unroll
            for (int nt = 0; nt < 8; nt++)
#pragma unroll
                for (int q = 0; q < 4; q++) acc[mt][nt][q] = 0.f;

        for (int kc = 0; kc < 10; kc++) {
            int s = kc & 1;
            if (sub == 3 && kc == 9) cp_wait0(); else cp_wait1();
            __syncthreads();

            uint32_t aB = sbase + aoff[s] + aAdd;
            uint32_t bB = sbase + boff[s] + bAdd;
#pragma unroll
            for (int ks = 0; ks < 4; ks++) {
                uint32_t a[2][4], b[8][2];
                ldm4(a[0], aB + ks * 32);
                ldm4(a[1], aB + 16 * 144 + ks * 32);
#pragma unroll
                for (int p = 0; p < 4; p++)
                    ldm4(&b[2 * p][0], bB + p * (16 * 144) + ks * 32);
#pragma unroll
                for (int mt = 0; mt < 2; mt++)
#pragma unroll
                    for (int nt = 0; nt < 8; nt++)
                        mma16816(acc[mt][nt], a[mt], b[nt]);
            }
            __syncthreads();
            if (kc + 2 < 10)      load_stage(sub, kc + 2, s);
            else if (sub < 3)     load_stage(sub + 1, kc + 2 - 10, s);
        }

        // ---- epilogue: bias add + store logits
#pragma unroll
        for (int mt = 0; mt < 2; mt++) {
#pragma unroll
            for (int nt = 0; nt < 8; nt++) {
                int row = m0 + m_base + mt * 16 + gid;
                int col = n0 + sub * 128 + n_base + nt * 8 + tig * 2;
                float2 bi = *(const float2*)(bias + col);
                float* p0 = out + (size_t)row * VV + col;
                p0[0] = acc[mt][nt][0] + bi.x;
                p0[1] = acc[mt][nt][1] + bi.y;
                float* p1 = out + (size_t)(row + 8) * VV + col;
                p1[0] = acc[mt][nt][2] + bi.x;
                p1[1] = acc[mt][nt][3] + bi.y;
            }
        }
    }
}

// ---------------------------------------------------------------------------
// K3: in-place log_softmax over last dim (V=1025).
// Warp-per-row: barrier-free, shfl-only reductions, fully-coalesced loads
// (lane j reads cols j, j+32, ..., j+992; each load instr = 128B contiguous).
// 8 warps (8 rows) per 256-thread block.
// ---------------------------------------------------------------------------
__global__ void __launch_bounds__(256) k_lsm(float* __restrict__ out) {
    int warp = threadIdx.x >> 5, lane = threadIdx.x & 31;
    int row = blockIdx.x * 8 + warp;
    float* p = out + (size_t)row * VV;

    float v[32];
#pragma unroll
    for (int j = 0; j < 32; j++) v[j] = p[lane + j * 32];
    float vb = (lane == 0) ? p[1024] : -1e30f;

    float mx = vb;
#pragma unroll
    for (int j = 0; j < 32; j++) mx = fmaxf(mx, v[j]);
#pragma unroll
    for (int o = 16; o; o >>= 1) mx = fmaxf(mx, __shfl_xor_sync(0xffffffffu, mx, o));

    float s = (lane == 0) ? __expf(vb - mx) : 0.f;
#pragma unroll
    for (int j = 0; j < 32; j++) s += __expf(v[j] - mx);
#pragma unroll
    for (int o = 16; o; o >>= 1) s += __shfl_xor_sync(0xffffffffu, s, o);

    float lse = mx + __logf(s);

#pragma unroll
    for (int j = 0; j < 32; j++) p[lane + j * 32] = v[j] - lse;
    if (lane == 0) p[1024] = vb - lse;
}

// ---------------------------------------------------------------------------
extern "C" void kernel_launch(void* const* d_in, const int* in_sizes, int n_in,
                              void* d_out, int out_size) {
    (void)in_sizes; (void)n_in; (void)out_size;
    const float* enc  = (const float*)d_in[0];
    const float* dec  = (const float*)d_in[1];
    const float* W    = (const float*)d_in[2];
    const float* bias = (const float*)d_in[3];
    float* out = (float*)d_out;

    k_convW<<<(NPAD * HH / 2 + 255) / 256, 256>>>(W);
    k_tanhA<<<NROWS / 8, 256>>>(enc, dec, W, bias, out);

    cudaFuncSetAttribute(k_gemm, cudaFuncAttributeMaxDynamicSharedMemorySize, SMEM_TOTAL);
    dim3 grid(NPAD / 512, NROWS / 128);   // (2, 1024)
    k_gemm<<<grid, 256, SMEM_TOTAL>>>(bias, out);

    k_lsm<<<NROWS / 8, 256>>>(out);
}